// round 7
// baseline (speedup 1.0000x reference)
#include <cuda_runtime.h>
#include <math.h>

#define Hn   2048
#define SEQ  2048
#define NBLK 148
#define TPB  288     // 8 worker warps (256) + 1 poller warp
#define WTH  256
#define MAXR 14      // max rows per block: ceil(2048/148)

typedef unsigned long long ull;

// ------------------------------------------------------------------
// Static device scratch (no cudaMalloc allowed)
// ------------------------------------------------------------------
__device__ float d_XF[SEQ * Hn];   // x @ Wfx^T + bfx
__device__ float d_XH[SEQ * Hn];   // x @ Whx^T + bhx
__device__ float d_hbuf[Hn];       // hidden state (cross-block)
__device__ float d_gbuf[Hn];       // f * h (cross-block)
__device__ unsigned d_count = 0;   // monotonic barrier arrival counter
__device__ unsigned d_base  = 0;   // counter value at start of this run

__device__ __forceinline__ void red_arrive(unsigned* p) {
    asm volatile("red.release.gpu.global.add.u32 [%0], %1;"
                 :: "l"(p), "r"(1u) : "memory");
}
__device__ __forceinline__ unsigned ld_acq(const unsigned* p) {
    unsigned v;
    asm volatile("ld.acquire.gpu.global.u32 %0, [%1];" : "=r"(v) : "l"(p) : "memory");
    return v;
}
// packed dual-fp32 FMA: d = a*b + d (lanewise on 2 floats)
__device__ __forceinline__ void fma2(ull &d, ull a, ull b) {
    asm volatile("fma.rn.f32x2 %0, %1, %2, %3;" : "=l"(d) : "l"(a), "l"(b), "l"(d));
}
__device__ __forceinline__ float lo_f(ull v) { return __uint_as_float((unsigned)v); }
__device__ __forceinline__ float hi_f(ull v) { return __uint_as_float((unsigned)(v >> 32)); }

// workers-only barrier
__device__ __forceinline__ void bar1() {
    asm volatile("bar.sync 1, %0;" :: "n"(WTH) : "memory");
}
// workers + poller barrier
__device__ __forceinline__ void bar2() {
    asm volatile("bar.sync 2, %0;" :: "n"(TPB) : "memory");
}

// ------------------------------------------------------------------
// Precompute GEMM:  C[s][n] = sum_k x[s][k] * W[n][k] + bias[n]
// Inner product in packed f32x2: 32 fma2 + 8 packs per k-iter.
// ------------------------------------------------------------------
__global__ __launch_bounds__(256, 2) void mgu_gemm(
    const float* __restrict__ x,
    const float* __restrict__ Wfx, const float* __restrict__ bfx,
    const float* __restrict__ Whx, const float* __restrict__ bhx)
{
    const float* __restrict__ W    = (blockIdx.z == 0) ? Wfx : Whx;
    const float* __restrict__ bias = (blockIdx.z == 0) ? bfx : bhx;
    float* __restrict__ C          = (blockIdx.z == 0) ? d_XF : d_XH;

    __shared__ float As[16][132];
    __shared__ float Bs[16][132];

    const int bm  = blockIdx.y * 128;
    const int bn  = blockIdx.x * 128;
    const int tid = threadIdx.x;
    const int tr  = (tid >> 4) << 3;
    const int tc  = (tid & 15) << 3;

    ull acc2[4][8];      // row-pairs x 8 cols, packed (row 2i, row 2i+1)
#pragma unroll
    for (int i = 0; i < 4; i++)
#pragma unroll
        for (int j = 0; j < 8; j++) acc2[i][j] = 0ull;

    for (int k0 = 0; k0 < 2048; k0 += 16) {
#pragma unroll
        for (int i = 0; i < 2; i++) {
            int q   = tid + (i << 8);
            int row = q >> 2;
            int kq  = (q & 3) << 2;
            float4 va = *(const float4 *)(x + (size_t)(bm + row) * 2048 + k0 + kq);
            As[kq + 0][row] = va.x; As[kq + 1][row] = va.y;
            As[kq + 2][row] = va.z; As[kq + 3][row] = va.w;
            float4 vb = *(const float4 *)(W + (size_t)(bn + row) * 2048 + k0 + kq);
            Bs[kq + 0][row] = vb.x; Bs[kq + 1][row] = vb.y;
            Bs[kq + 2][row] = vb.z; Bs[kq + 3][row] = vb.w;
        }
        __syncthreads();
#pragma unroll
        for (int k = 0; k < 16; k++) {
            // row pairs come packed for free from the contiguous A tile
            ulonglong2 a01 = *(const ulonglong2 *)&As[k][tr];      // (a0,a1),(a2,a3)
            ulonglong2 a23 = *(const ulonglong2 *)&As[k][tr + 4];  // (a4,a5),(a6,a7)
            ull ap[4] = {a01.x, a01.y, a23.x, a23.y};
            float bsv[8];
            *(float4 *)(bsv)     = *(const float4 *)&Bs[k][tc];
            *(float4 *)(bsv + 4) = *(const float4 *)&Bs[k][tc + 4];
            ull bd[8];
#pragma unroll
            for (int j = 0; j < 8; j++)
                asm("mov.b64 %0, {%1, %1};" : "=l"(bd[j]) : "f"(bsv[j]));
#pragma unroll
            for (int i = 0; i < 4; i++)
#pragma unroll
                for (int j = 0; j < 8; j++) fma2(acc2[i][j], ap[i], bd[j]);
        }
        __syncthreads();
    }

    float bj[8];
#pragma unroll
    for (int j = 0; j < 8; j++) bj[j] = __ldg(&bias[bn + tc + j]);
#pragma unroll
    for (int i = 0; i < 4; i++) {
#pragma unroll
        for (int p = 0; p < 2; p++) {
            float v[8];
#pragma unroll
            for (int j = 0; j < 8; j++)
                v[j] = (p ? hi_f(acc2[i][j]) : lo_f(acc2[i][j])) + bj[j];
            size_t off = (size_t)(bm + tr + 2 * i + p) * 2048 + bn + tc;
            *(float4 *)(C + off)     = make_float4(v[0], v[1], v[2], v[3]);
            *(float4 *)(C + off + 4) = make_float4(v[4], v[5], v[6], v[7]);
        }
    }
}

// ------------------------------------------------------------------
// Persistent scan. 148 blocks (1/SM). Warps 0-7 = workers, warp 8 =
// poller. GEMV inner products in packed f32x2 (halved FFMA pipe).
// Weights preloaded into regs during the barrier window.
// ------------------------------------------------------------------
__global__ __launch_bounds__(TPB, 1) void mgu_scan(
    const float* __restrict__ h0,
    const float* __restrict__ Wfh, const float* __restrict__ bfh,
    const float* __restrict__ Whf, const float* __restrict__ bhf,
    float* __restrict__ out)
{
    extern __shared__ float sW[];
    __shared__ float sPart[MAXR][8];
    __shared__ float sF[MAXR];
    __shared__ float sHold[MAXR];
    __shared__ float sBfh[MAXR];
    __shared__ float sBhf[MAXR];
    __shared__ unsigned sBase;

    const int b   = blockIdx.x;
    const int tid = threadIdx.x;
    const int r0  = (b * Hn) / NBLK;
    const int r1  = ((b + 1) * Hn) / NBLK;
    const int nr  = r1 - r0;               // 13 or 14

    float* sWf = sW;                        // Wfh rows
    float* sWh = sW + nr * Hn;              // Whf rows

    if (tid == 0) sBase = *(volatile unsigned *)&d_base;

    {   // stage weight rows into SMEM (coalesced float4)
        const float4* gf = (const float4 *)(Wfh + (size_t)r0 * Hn);
        const float4* gh = (const float4 *)(Whf + (size_t)r0 * Hn);
        float4* sf4 = (float4 *)sWf;
        float4* sh4 = (float4 *)sWh;
        const int n4 = nr * (Hn / 4);
        for (int i = tid; i < n4; i += TPB) { sf4[i] = gf[i]; sh4[i] = gh[i]; }
    }
    if (tid < nr) {
        sBfh[tid]  = bfh[r0 + tid];
        sBhf[tid]  = bhf[r0 + tid];
        sHold[tid] = h0[r0 + tid];
    }
    for (int i = b * TPB + tid; i < Hn; i += NBLK * TPB) d_hbuf[i] = h0[i];

    __syncthreads();
    const unsigned base = sBase;
    if (tid == 0) red_arrive(&d_count);      // gen 1: weights + h0 published

    // ---------------- poller warp ----------------
    if (tid >= WTH) {
        for (unsigned g = 1; g <= 2u * SEQ; g++) {
            if (tid == WTH) {
                unsigned target = base + g * (unsigned)NBLK;
                while ((int)(ld_acq(&d_count) - target) < 0) { }
            }
            bar2();
        }
        if (b == 0 && tid == WTH)
            *(volatile unsigned *)&d_base = base + 2u * SEQ * (unsigned)NBLK;
        return;
    }

    // ---------------- workers ----------------
    const int lane = tid & 31;
    const int wid  = tid >> 5;
    const int cA   = wid * 128 + lane * 4;          // conflict-free chunk 0
    const int cB   = 1024 + wid * 128 + lane * 4;   // conflict-free chunk 1

    float xf_c = 0.f, xh_c = 0.f;
    if (tid < nr) {
        xf_c = __ldg(&d_XF[r0 + tid]);
        xh_c = __ldg(&d_XH[r0 + tid]);
    }

    ulonglong2 wr[MAXR][2];                          // packed weight pairs
#pragma unroll
    for (int r = 0; r < MAXR; r++) {                 // preload Wfh for t=0
        wr[r][0] = *(const ulonglong2 *)(sWf + r * Hn + cA);
        wr[r][1] = *(const ulonglong2 *)(sWf + r * Hn + cB);
    }
    bar2();                                          // gen 1 synced: h ready

    for (int t = 0; t < SEQ; t++) {
        // ===== phase A : f = sigmoid(xf + Wfh h + bfh);  g = f*h =====
        ulonglong2 hv0 = __ldcg((const ulonglong2 *)&d_hbuf[cA]);
        ulonglong2 hv1 = __ldcg((const ulonglong2 *)&d_hbuf[cB]);

        float acc[MAXR];
#pragma unroll
        for (int r = 0; r < MAXR; r++) {
            ull a2 = 0ull;
            fma2(a2, wr[r][0].x, hv0.x);
            fma2(a2, wr[r][0].y, hv0.y);
            fma2(a2, wr[r][1].x, hv1.x);
            fma2(a2, wr[r][1].y, hv1.y);
            acc[r] = lo_f(a2) + hi_f(a2);
        }
        // paired butterfly reduction: 6 SHFL per 2 rows
#pragma unroll
        for (int p = 0; p < 7; p++) {
            float a = acc[2 * p], c = acc[2 * p + 1];
            a += __shfl_xor_sync(0xffffffffu, a, 16);
            c += __shfl_xor_sync(0xffffffffu, c, 16);
            float m = (lane < 16) ? a : c;
            m += __shfl_xor_sync(0xffffffffu, m, 8);
            m += __shfl_xor_sync(0xffffffffu, m, 4);
            m += __shfl_xor_sync(0xffffffffu, m, 2);
            m += __shfl_xor_sync(0xffffffffu, m, 1);
            if (lane == 0)       sPart[2 * p][wid]     = m;
            else if (lane == 16) sPart[2 * p + 1][wid] = m;
        }
        bar1();
        if (tid < 32) {                              // tail lives in warp 0
            if (tid < nr) {
                float4 p0 = *(const float4 *)&sPart[tid][0];
                float4 p1 = *(const float4 *)&sPart[tid][4];
                float s = (p0.x + p0.y) + (p0.z + p0.w)
                        + (p1.x + p1.y) + (p1.z + p1.w);
                float z = s + sBfh[tid] + xf_c;
                float f = 1.f / (1.f + __expf(-z));
                sF[tid] = f;
                __stcg(&d_gbuf[r0 + tid], f * sHold[tid]);
            }
            __syncwarp();
            if (tid == 0) red_arrive(&d_count);      // gen 2t+2
        }
#pragma unroll
        for (int r = 0; r < MAXR; r++) {             // preload Whf (hidden under sync)
            wr[r][0] = *(const ulonglong2 *)(sWh + r * Hn + cA);
            wr[r][1] = *(const ulonglong2 *)(sWh + r * Hn + cB);
        }
        bar2();                                      // gen 2t+2 synced: g ready

        // ===== phase B : h_hat = tanh(Whf g + bhf + xh); update =====
        ulonglong2 gv0 = __ldcg((const ulonglong2 *)&d_gbuf[cA]);
        ulonglong2 gv1 = __ldcg((const ulonglong2 *)&d_gbuf[cB]);

        float xf_n = 0.f, xh_n = 0.f;                // prefetch next x-projections
        if (tid < nr && t + 1 < SEQ) {
            xf_n = __ldg(&d_XF[(size_t)(t + 1) * Hn + r0 + tid]);
            xh_n = __ldg(&d_XH[(size_t)(t + 1) * Hn + r0 + tid]);
        }

#pragma unroll
        for (int r = 0; r < MAXR; r++) {
            ull a2 = 0ull;
            fma2(a2, wr[r][0].x, gv0.x);
            fma2(a2, wr[r][0].y, gv0.y);
            fma2(a2, wr[r][1].x, gv1.x);
            fma2(a2, wr[r][1].y, gv1.y);
            acc[r] = lo_f(a2) + hi_f(a2);
        }
#pragma unroll
        for (int p = 0; p < 7; p++) {
            float a = acc[2 * p], c = acc[2 * p + 1];
            a += __shfl_xor_sync(0xffffffffu, a, 16);
            c += __shfl_xor_sync(0xffffffffu, c, 16);
            float m = (lane < 16) ? a : c;
            m += __shfl_xor_sync(0xffffffffu, m, 8);
            m += __shfl_xor_sync(0xffffffffu, m, 4);
            m += __shfl_xor_sync(0xffffffffu, m, 2);
            m += __shfl_xor_sync(0xffffffffu, m, 1);
            if (lane == 0)       sPart[2 * p][wid]     = m;
            else if (lane == 16) sPart[2 * p + 1][wid] = m;
        }
        bar1();
        if (tid < 32) {
            if (tid < nr) {
                float4 p0 = *(const float4 *)&sPart[tid][0];
                float4 p1 = *(const float4 *)&sPart[tid][4];
                float s = (p0.x + p0.y) + (p0.z + p0.w)
                        + (p1.x + p1.y) + (p1.z + p1.w);
                float z  = s + sBhf[tid] + xh_c;
                float e2 = __expf(2.f * z);
                float hh = 1.f - 2.f / (e2 + 1.f);      // tanh(z)
                float f  = sF[tid];
                float ho = sHold[tid];
                float hn = ho + f * (hh - ho);          // (1-f)*h + f*h_hat
                sHold[tid] = hn;
                int row = r0 + tid;
                out[(size_t)t * Hn + row] = hn;
                __stcg(&d_hbuf[row], hn);
                if (t == SEQ - 1) out[(size_t)SEQ * Hn + row] = hn;  // h_final
            }
            __syncwarp();
            if (tid == 0 && t < SEQ - 1) red_arrive(&d_count);   // gen 2t+3
        }
        if (t < SEQ - 1) {
#pragma unroll
            for (int r = 0; r < MAXR; r++) {         // preload Wfh for next step
                wr[r][0] = *(const ulonglong2 *)(sWf + r * Hn + cA);
                wr[r][1] = *(const ulonglong2 *)(sWf + r * Hn + cB);
            }
            bar2();                                  // gen 2t+3 synced: h ready
        }
        xf_c = xf_n;
        xh_c = xh_n;
    }
}

// ------------------------------------------------------------------
extern "C" void kernel_launch(void* const* d_in, const int* in_sizes, int n_in,
                              void* d_out, int out_size)
{
    const float* x   = (const float *)d_in[0];
    const float* h0  = (const float *)d_in[1];
    const float* Wfx = (const float *)d_in[2];
    const float* bfx = (const float *)d_in[3];
    const float* Wfh = (const float *)d_in[4];
    const float* bfh = (const float *)d_in[5];
    const float* Whf = (const float *)d_in[6];
    const float* bhf = (const float *)d_in[7];
    const float* Whx = (const float *)d_in[8];
    const float* bhx = (const float *)d_in[9];
    float* out = (float *)d_out;

    (void)in_sizes; (void)n_in; (void)out_size;

    const size_t smem = (size_t)MAXR * Hn * 2 * sizeof(float);  // 229376 B
    cudaFuncSetAttribute(mgu_scan, cudaFuncAttributeMaxDynamicSharedMemorySize,
                         (int)smem);

    mgu_gemm<<<dim3(16, 16, 2), 256>>>(x, Wfx, bfx, Whx, bhx);
    mgu_scan<<<NBLK, TPB, smem>>>(h0, Wfh, bfh, Whf, bhf, out);
}